// round 13
// baseline (speedup 1.0000x reference)
#include <cuda_runtime.h>

#define NPTS   8192
#define BATCH  4
#define TPB    128
#define QTY    8                 // ty groups (query dim)
#define QPT    8                 // queries per thread (lane-duplicated packs)
#define QB     (QTY*QPT)         // 64 queries per block
#define NQT    (NPTS/QB)         // 128 query tiles
#define TTX    16                // tx groups (target dim)
#define TPP    32                // packed target-pairs per thread (64 targets)
#define TB     (TTX*TPP*2)       // 1024 targets per block
#define NTT    (NPTS/TB)         // 8 target tiles
#define NPAIR  (TB/2)            // 512 target pairs per block
#define NCOPY  (QTY/2)           // 4 sRed copies (warp-folded via shfl)
#define QSTR   (QB+1)            // padded stride for q-dir smem reduce (65)
#define NBLK2  256

__device__ float g_qpart[NTT][BATCH][NPTS];   // pred-side partial min-d2 (1MB)
__device__ float g_tpart[NQT][BATCH][NPTS];   // targ-side partial min-d2 (16.8MB)
__device__ float g_partials[NBLK2];

__device__ __forceinline__ unsigned long long ffma2(unsigned long long a,
                                                    unsigned long long b,
                                                    unsigned long long c) {
    unsigned long long d;
    asm("fma.rn.f32x2 %0, %1, %2, %3;" : "=l"(d) : "l"(a), "l"(b), "l"(c));
    return d;
}
__device__ __forceinline__ unsigned long long mul2(unsigned long long a,
                                                   unsigned long long b) {
    unsigned long long d;
    asm("mul.rn.f32x2 %0, %1, %2;" : "=l"(d) : "l"(a), "l"(b));
    return d;
}
__device__ __forceinline__ unsigned long long add2(unsigned long long a,
                                                   unsigned long long b) {
    unsigned long long d;
    asm("add.rn.f32x2 %0, %1, %2;" : "=l"(d) : "l"(a), "l"(b));
    return d;
}
__device__ __forceinline__ unsigned long long pack2(float lo, float hi) {
    unsigned long long r;
    asm("mov.b64 %0, {%1, %2};" : "=l"(r) : "f"(lo), "f"(hi));
    return r;
}
__device__ __forceinline__ float2 unpack2(unsigned long long v) {
    float2 r;
    asm("mov.b64 {%0, %1}, %2;" : "=f"(r.x), "=f"(r.y) : "l"(v));
    return r;
}

// Block = (query-tile of 64, target-tile of 1024, batch). One pass computes
// u = d^2 = |p|^2 + |t|^2 - 2 p.t per pair (2 targets per f32x2).
// Smem carries only (x,y) float4 pairs + packed z pairs (24B/lane/jj);
// |t|^2 is recomputed once per jj (3 f32x2 amortized over 8 queries).
// Query constants pre-scaled: npx=-2x, gpk=|p|^2 -> same 4 ops per query.
__global__ __launch_bounds__(TPB, 6)
void chamfer_pair_kernel(const float* __restrict__ pred,
                         const float* __restrict__ targ) {
    __shared__ float4 sA[NPAIR];                 // (x0,x1, y0,y1)   8KB
    __shared__ unsigned long long sZ[NPAIR];     // (z0,z1)          4KB
    __shared__ unsigned long long sRed[NCOPY * NPAIR];   // 16KB reduce buffer

    const int tid = threadIdx.x;
    const int tx  = tid & 15;
    const int ty  = tid >> 4;
    const int wid = tid >> 5;     // warp id = ty>>1
    const int qt  = blockIdx.x;   // 0..127
    const int tt  = blockIdx.y;   // 0..7
    const int b   = blockIdx.z;   // 0..3

    const float* P = pred + b * 3 * NPTS;
    const float* T = targ + b * 3 * NPTS;

    // ---- stage this tile's 1024 targets (two float4-groups per thread) ----
    {
        const float* Tx = T + tt * TB;
        const float* Ty = Tx + NPTS;
        const float* Tz = Tx + 2 * NPTS;
#pragma unroll
        for (int i = 0; i < 2; i++) {
            const int g4 = tid + i * TPB;       // float4-group 0..255
            const int m  = g4 * 4;
            const float4 x4 = *reinterpret_cast<const float4*>(Tx + m);
            const float4 y4 = *reinterpret_cast<const float4*>(Ty + m);
            const float4 z4 = *reinterpret_cast<const float4*>(Tz + m);
            sA[2 * g4]     = make_float4(x4.x, x4.y, y4.x, y4.y);
            sZ[2 * g4]     = pack2(z4.x, z4.y);
            sA[2 * g4 + 1] = make_float4(x4.z, x4.w, y4.z, y4.w);
            sZ[2 * g4 + 1] = pack2(z4.z, z4.w);
        }
    }

    // ---- load this thread's 8 register queries (scaled, lane-dup packs) ----
    unsigned long long npx[QPT], npy[QPT], npz[QPT], gpk[QPT];
    float accl[QPT], acch[QPT];
#pragma unroll
    for (int q = 0; q < QPT; q++) {
        const int idx = qt * QB + ty * QPT + q;
        const float x = P[idx];
        const float y = P[NPTS + idx];
        const float z = P[2 * NPTS + idx];
        npx[q] = pack2(-2.f * x, -2.f * x);
        npy[q] = pack2(-2.f * y, -2.f * y);
        npz[q] = pack2(-2.f * z, -2.f * z);
        const float g = x * x + y * y + z * z;   // |p|^2
        gpk[q] = pack2(g, g);
        accl[q] = 1e30f;
        acch[q] = 1e30f;
    }
    __syncthreads();

    const ulonglong2* A = reinterpret_cast<const ulonglong2*>(sA);

#pragma unroll 8
    for (int jj = 0; jj < TPP; ++jj) {
        const int j = jj * TTX + tx;       // lane-consecutive: conflict-free
        const ulonglong2 av = A[j];        // (x0,x1), (y0,y1)
        const unsigned long long zv = sZ[j];   // (z0,z1)
        // H = |t|^2 for the pair (amortized over the 8 queries)
        unsigned long long Hv = mul2(av.x, av.x);
        Hv = ffma2(av.y, av.y, Hv);
        Hv = ffma2(zv, zv, Hv);
        float tl0, tl1, th0, th1;          // 4 running t-side chains
#pragma unroll
        for (int q = 0; q < QPT; q++) {
            unsigned long long u = ffma2(npx[q], av.x, Hv);  // |t|^2 - 2x.tx
            u = ffma2(npy[q], av.y, u);
            u = ffma2(npz[q], zv, u);
            u = add2(gpk[q], u);                // u = d^2
            const float2 uf = unpack2(u);
            accl[q] = fminf(accl[q], uf.x);     // pred side (per query)
            acch[q] = fminf(acch[q], uf.y);
            if (q == 0)      { tl0 = uf.x; th0 = uf.y; }
            else if (q == 1) { tl1 = uf.x; th1 = uf.y; }
            else if (q & 1)  { tl1 = fminf(tl1, uf.x); th1 = fminf(th1, uf.y); }
            else             { tl0 = fminf(tl0, uf.x); th0 = fminf(th0, uf.y); }
        }
        float tl = fminf(tl0, tl1);
        float th = fminf(th0, th1);
        // fold the two half-warps (ty = 2w, 2w+1) before storing
        tl = fminf(tl, __shfl_xor_sync(0xFFFFFFFFu, tl, 16));
        th = fminf(th, __shfl_xor_sync(0xFFFFFFFFu, th, 16));
        if ((ty & 1) == 0)
            sRed[wid * NPAIR + j] = pack2(tl, th);
    }
    __syncthreads();

    // ---- t-direction: min over the 4 warp copies, write 1024 partials ----
#pragma unroll
    for (int oo = 0; oo < 4; oo++) {
        const int o = oo * TPB + tid;      // pair index 0..511, lanes consecutive
        float2 m = unpack2(sRed[o]);
#pragma unroll
        for (int t2 = 1; t2 < NCOPY; t2++) {
            const float2 v = unpack2(sRed[t2 * NPAIR + o]);
            m.x = fminf(m.x, v.x);
            m.y = fminf(m.y, v.y);
        }
        float* dst = &g_tpart[qt][b][tt * TB + 2 * o];   // pair o = targets 2o,2o+1
        dst[0] = m.x;
        dst[1] = m.y;
    }
    __syncthreads();

    // ---- q-direction: stage packed accs (padded stride), min over 16 tx ----
#pragma unroll
    for (int q = 0; q < QPT; q++)
        sRed[tx * QSTR + ty * QPT + q] = pack2(accl[q], acch[q]);
    __syncthreads();

    if (tid < QB) {
        float2 m = unpack2(sRed[tid]);
#pragma unroll
        for (int t2 = 1; t2 < TTX; t2++) {
            const float2 v = unpack2(sRed[t2 * QSTR + tid]);
            m.x = fminf(m.x, v.x);
            m.y = fminf(m.y, v.y);
        }
        g_qpart[tt][b][qt * QB + tid] = fminf(m.x, m.y);
    }
}

// Combine: min over tiles, d = sqrt(max(u,0)), deterministic block sums.
__global__ __launch_bounds__(256)
void chamfer_combine(float* __restrict__ dummy) {
    __shared__ float red[8];
    const int tid = threadIdx.x;
    const int gp  = blockIdx.x * 256 + tid;   // 0..65535

    float u;
    if (gp < BATCH * NPTS) {                  // pred side: min over target tiles
        const int b   = gp >> 13;
        const int idx = gp & (NPTS - 1);
        u = g_qpart[0][b][idx];
#pragma unroll
        for (int t = 1; t < NTT; t++) u = fminf(u, g_qpart[t][b][idx]);
    } else {                                  // targ side: min over query tiles
        const int g2  = gp - BATCH * NPTS;
        const int b   = g2 >> 13;
        const int idx = g2 & (NPTS - 1);
        u = g_tpart[0][b][idx];
#pragma unroll 8
        for (int t = 1; t < NQT; t++) u = fminf(u, g_tpart[t][b][idx]);
    }

    float d = sqrtf(fmaxf(u, 0.f));           // u is already d^2
#pragma unroll
    for (int off = 16; off > 0; off >>= 1)
        d += __shfl_down_sync(0xFFFFFFFFu, d, off);
    if ((tid & 31) == 0) red[tid >> 5] = d;
    __syncthreads();
    if (tid == 0) {
        float t = 0.f;
#pragma unroll
        for (int w = 0; w < 8; w++) t += red[w];
        g_partials[blockIdx.x] = t;
    }
}

// Deterministic final reduction of the 256 block partials.
__global__ void chamfer_reduce(float* __restrict__ out) {
    __shared__ float red[8];
    const int tid = threadIdx.x;
    float v = g_partials[tid];
#pragma unroll
    for (int off = 16; off > 0; off >>= 1)
        v += __shfl_down_sync(0xFFFFFFFFu, v, off);
    if ((tid & 31) == 0) red[tid >> 5] = v;
    __syncthreads();
    if (tid == 0) {
        float s = 0.f;
#pragma unroll
        for (int w = 0; w < 8; w++) s += red[w];
        out[0] = s * (1.0f / (BATCH * NPTS));
    }
}

extern "C" void kernel_launch(void* const* d_in, const int* in_sizes, int n_in,
                              void* d_out, int out_size) {
    const float* pred = (const float*)d_in[0];
    const float* targ = (const float*)d_in[1];
    float* out = (float*)d_out;

    dim3 grid(NQT, NTT, BATCH);   // 128 x 8 x 4 = 4096 blocks
    chamfer_pair_kernel<<<grid, TPB>>>(pred, targ);
    chamfer_combine<<<NBLK2, 256>>>(out);
    chamfer_reduce<<<1, 256>>>(out);
}

// round 14
// speedup vs baseline: 1.5522x; 1.5522x over previous
#include <cuda_runtime.h>

#define NPTS   8192
#define BATCH  4
#define TPB    128
#define QTY    8                 // ty groups (query dim)
#define QPT    8                 // queries per thread per pass
#define QB     (QTY*QPT)         // 64 queries per pass
#define QI     2                 // query passes per block
#define QBB    (QB*QI)           // 128 queries per block
#define NQT    (NPTS/QBB)        // 64 query tiles
#define TTX    16                // tx groups (target dim)
#define TPP    32                // packed target-pairs per thread (64 targets)
#define TB     (TTX*TPP*2)       // 1024 targets per block
#define NTT    (NPTS/TB)         // 8 target tiles
#define NPAIR  (TB/2)            // 512 target pairs per block
#define NCOPY  (QTY/2)           // 4 sRed copies (warp-folded via shfl)
#define QSTR   (QB+1)            // padded stride for q-dir smem reduce (65)
#define NBLK2  256

__device__ float g_qpart[NTT][BATCH][NPTS];   // pred-side partial min-u (1MB)
__device__ float g_tpart[NQT][BATCH][NPTS];   // targ-side partial min-u (8.4MB)
__device__ float g_partials[NBLK2];
__device__ int   g_counter;                   // last-block ticket (reset each run)

__device__ __forceinline__ unsigned long long ffma2(unsigned long long a,
                                                    unsigned long long b,
                                                    unsigned long long c) {
    unsigned long long d;
    asm("fma.rn.f32x2 %0, %1, %2, %3;" : "=l"(d) : "l"(a), "l"(b), "l"(c));
    return d;
}
__device__ __forceinline__ unsigned long long add2(unsigned long long a,
                                                   unsigned long long b) {
    unsigned long long d;
    asm("add.rn.f32x2 %0, %1, %2;" : "=l"(d) : "l"(a), "l"(b));
    return d;
}
__device__ __forceinline__ unsigned long long pack2(float lo, float hi) {
    unsigned long long r;
    asm("mov.b64 %0, {%1, %2};" : "=l"(r) : "f"(lo), "f"(hi));
    return r;
}
__device__ __forceinline__ float2 unpack2(unsigned long long v) {
    float2 r;
    asm("mov.b64 {%0, %1}, %2;" : "=f"(r.x), "=f"(r.y) : "l"(v));
    return r;
}

// Block = (query-tile of 128 via 2 passes of 64, target-tile of 1024, batch).
// u = 0.5*d^2 = g + h - p.t per pair (2 targets per f32x2).
//   min over targets -> g_qpart (per pass); min over queries -> g_tpart
//   (sRed folded across passes by same-thread read-min-write).
__global__ __launch_bounds__(TPB, 6)
void chamfer_pair_kernel(const float* __restrict__ pred,
                         const float* __restrict__ targ) {
    __shared__ float4 sA[NPAIR];   // (x0,x1, y0,y1) per target pair   8KB
    __shared__ float4 sB[NPAIR];   // (z0,z1, h0,h1)                   8KB
    __shared__ unsigned long long sRed[NCOPY * NPAIR];   // 16KB t-side buffer
    __shared__ float sQ[TTX * QSTR];                     // 4.2KB q-side buffer

    const int tid = threadIdx.x;
    const int tx  = tid & 15;
    const int ty  = tid >> 4;
    const int wid = tid >> 5;     // warp id = ty>>1
    const int qt  = blockIdx.x;   // 0..63
    const int tt  = blockIdx.y;   // 0..7
    const int b   = blockIdx.z;   // 0..3

    const float* P = pred + b * 3 * NPTS;
    const float* T = targ + b * 3 * NPTS;

    // ---- stage this tile's 1024 targets (two float4-groups per thread) ----
    {
        const float* Tx = T + tt * TB;
        const float* Ty = Tx + NPTS;
        const float* Tz = Tx + 2 * NPTS;
#pragma unroll
        for (int i = 0; i < 2; i++) {
            const int g4 = tid + i * TPB;       // float4-group 0..255
            const int m  = g4 * 4;
            const float4 x4 = *reinterpret_cast<const float4*>(Tx + m);
            const float4 y4 = *reinterpret_cast<const float4*>(Ty + m);
            const float4 z4 = *reinterpret_cast<const float4*>(Tz + m);
            const float h0 = 0.5f * (x4.x * x4.x + y4.x * y4.x + z4.x * z4.x);
            const float h1 = 0.5f * (x4.y * x4.y + y4.y * y4.y + z4.y * z4.y);
            const float h2 = 0.5f * (x4.z * x4.z + y4.z * y4.z + z4.z * z4.z);
            const float h3 = 0.5f * (x4.w * x4.w + y4.w * y4.w + z4.w * z4.w);
            sA[2 * g4]     = make_float4(x4.x, x4.y, y4.x, y4.y);
            sB[2 * g4]     = make_float4(z4.x, z4.y, h0, h1);
            sA[2 * g4 + 1] = make_float4(x4.z, x4.w, y4.z, y4.w);
            sB[2 * g4 + 1] = make_float4(z4.z, z4.w, h2, h3);
        }
    }
    __syncthreads();

    const ulonglong2* A  = reinterpret_cast<const ulonglong2*>(sA);
    const ulonglong2* Bq = reinterpret_cast<const ulonglong2*>(sB);

    for (int qi = 0; qi < QI; qi++) {
        // ---- load this pass's 8 register queries (lane-duplicated packs) ----
        unsigned long long npx[QPT], npy[QPT], npz[QPT], gpk[QPT];
        float accl[QPT], acch[QPT];
#pragma unroll
        for (int q = 0; q < QPT; q++) {
            const int idx = qt * QBB + qi * QB + ty * QPT + q;
            const float x = P[idx];
            const float y = P[NPTS + idx];
            const float z = P[2 * NPTS + idx];
            npx[q] = pack2(-x, -x);
            npy[q] = pack2(-y, -y);
            npz[q] = pack2(-z, -z);
            const float g = 0.5f * (x * x + y * y + z * z);
            gpk[q] = pack2(g, g);
            accl[q] = 1e30f;
            acch[q] = 1e30f;
        }

#pragma unroll 8
        for (int jj = 0; jj < TPP; ++jj) {
            const int j = jj * TTX + tx;   // lane-consecutive: conflict-free
            const ulonglong2 av = A[j];    // (x0,x1), (y0,y1)
            const ulonglong2 bv = Bq[j];   // (z0,z1), (h0,h1)
            float tl0, tl1, th0, th1;      // 4 running t-side chains
#pragma unroll
            for (int q = 0; q < QPT; q++) {
                unsigned long long u = ffma2(npx[q], av.x, bv.y);  // h - x.tx
                u = ffma2(npy[q], av.y, u);
                u = ffma2(npz[q], bv.x, u);
                u = add2(gpk[q], u);            // u = g + h - p.t = d^2/2
                const float2 uf = unpack2(u);
                accl[q] = fminf(accl[q], uf.x); // pred side (per query)
                acch[q] = fminf(acch[q], uf.y);
                if (q == 0)      { tl0 = uf.x; th0 = uf.y; }
                else if (q == 1) { tl1 = uf.x; th1 = uf.y; }
                else if (q & 1)  { tl1 = fminf(tl1, uf.x); th1 = fminf(th1, uf.y); }
                else             { tl0 = fminf(tl0, uf.x); th0 = fminf(th0, uf.y); }
            }
            float tl = fminf(tl0, tl1);
            float th = fminf(th0, th1);
            // fold the two half-warps (ty = 2w, 2w+1) before storing
            tl = fminf(tl, __shfl_xor_sync(0xFFFFFFFFu, tl, 16));
            th = fminf(th, __shfl_xor_sync(0xFFFFFFFFu, th, 16));
            if ((ty & 1) == 0) {
                if (qi == 0) {
                    sRed[wid * NPAIR + j] = pack2(tl, th);
                } else {      // same thread owns this slot: safe read-min-write
                    const float2 o = unpack2(sRed[wid * NPAIR + j]);
                    sRed[wid * NPAIR + j] =
                        pack2(fminf(tl, o.x), fminf(th, o.y));
                }
            }
        }

        // ---- q-direction for this pass: fold lo/hi, min over 16 tx ----
#pragma unroll
        for (int q = 0; q < QPT; q++)
            sQ[tx * QSTR + ty * QPT + q] = fminf(accl[q], acch[q]);
        __syncthreads();
        if (tid < QB) {
            float m = sQ[tid];
#pragma unroll
            for (int t2 = 1; t2 < TTX; t2++) m = fminf(m, sQ[t2 * QSTR + tid]);
            g_qpart[tt][b][qt * QBB + qi * QB + tid] = m;
        }
        __syncthreads();   // protect sQ (and order sRed) before next pass
    }

    // ---- t-direction: min over the 4 warp copies, write 1024 partials ----
#pragma unroll
    for (int oo = 0; oo < 4; oo++) {
        const int o = oo * TPB + tid;      // pair index 0..511, lanes consecutive
        float2 m = unpack2(sRed[o]);
#pragma unroll
        for (int t2 = 1; t2 < NCOPY; t2++) {
            const float2 v = unpack2(sRed[t2 * NPAIR + o]);
            m.x = fminf(m.x, v.x);
            m.y = fminf(m.y, v.y);
        }
        float* dst = &g_tpart[qt][b][tt * TB + 2 * o];   // pair o = targets 2o,2o+1
        dst[0] = m.x;
        dst[1] = m.y;
    }
}

// Fused combine + final reduce (last-block finalize, deterministic order).
__global__ __launch_bounds__(256)
void chamfer_combine(float* __restrict__ out) {
    __shared__ float red[8];
    __shared__ int sLast;
    const int tid = threadIdx.x;
    const int gp  = blockIdx.x * 256 + tid;   // 0..65535

    float u;
    if (gp < BATCH * NPTS) {                  // pred side: min over target tiles
        const int b   = gp >> 13;
        const int idx = gp & (NPTS - 1);
        u = g_qpart[0][b][idx];
#pragma unroll
        for (int t = 1; t < NTT; t++) u = fminf(u, g_qpart[t][b][idx]);
    } else {                                  // targ side: min over query tiles
        const int g2  = gp - BATCH * NPTS;
        const int b   = g2 >> 13;
        const int idx = g2 & (NPTS - 1);
        u = g_tpart[0][b][idx];
#pragma unroll 8
        for (int t = 1; t < NQT; t++) u = fminf(u, g_tpart[t][b][idx]);
    }

    float d = sqrtf(fmaxf(2.f * u, 0.f));     // u = d^2/2
#pragma unroll
    for (int off = 16; off > 0; off >>= 1)
        d += __shfl_down_sync(0xFFFFFFFFu, d, off);
    if ((tid & 31) == 0) red[tid >> 5] = d;
    __syncthreads();
    if (tid == 0) {
        float t = 0.f;
#pragma unroll
        for (int w = 0; w < 8; w++) t += red[w];
        g_partials[blockIdx.x] = t;
        __threadfence();
        sLast = (atomicAdd(&g_counter, 1) == NBLK2 - 1);
    }
    __syncthreads();

    if (sLast) {                              // exactly one block finalizes
        __threadfence();
        float v = g_partials[tid];            // fixed-order deterministic sum
#pragma unroll
        for (int off = 16; off > 0; off >>= 1)
            v += __shfl_down_sync(0xFFFFFFFFu, v, off);
        if ((tid & 31) == 0) red[tid >> 5] = v;
        __syncthreads();
        if (tid == 0) {
            float s = 0.f;
#pragma unroll
            for (int w = 0; w < 8; w++) s += red[w];
            out[0] = s * (1.0f / (BATCH * NPTS));
            g_counter = 0;                    // reset for next graph replay
        }
    }
}

extern "C" void kernel_launch(void* const* d_in, const int* in_sizes, int n_in,
                              void* d_out, int out_size) {
    const float* pred = (const float*)d_in[0];
    const float* targ = (const float*)d_in[1];
    float* out = (float*)d_out;

    dim3 grid(NQT, NTT, BATCH);   // 64 x 8 x 4 = 2048 blocks
    chamfer_pair_kernel<<<grid, TPB>>>(pred, targ);
    chamfer_combine<<<NBLK2, 256>>>(out);
}